// round 15
// baseline (speedup 1.0000x reference)
#include <cuda_runtime.h>
#include <cuda_fp16.h>
#include <math.h>

#define N_ATOMS 50000
#define N_EDGES 100000
#define B_G 50
#define M_M 50
#define NPG 1000
#define DIN 32
#define H1D 32
#define H2D 64
#define DE 16
#define AAF 95
#define G_DIM 128
#define K_S 3
#define T_L 6
#define EA 98
#define F1D 64
#define F2D 32
#define F3D 16
#define X0DIM 159
#define X0PAD 160
#define NBUCK 1563    /* ceil(50000/32) */

typedef unsigned long long u64;

// ---------------- f32x2 helpers ----------------
__device__ __forceinline__ u64 pk2(float a, float b) {
    u64 r;
    asm("mov.b64 %0, {%1, %2};" : "=l"(r) : "f"(a), "f"(b));
    return r;
}
__device__ __forceinline__ void fma2(u64& d, u64 a, u64 b) {
    asm("fma.rn.f32x2 %0, %1, %2, %3;" : "=l"(d) : "l"(a), "l"(b), "l"(d));
}
__device__ __forceinline__ void add2(u64& d, u64 a) {
    asm("add.rn.f32x2 %0, %1, %2;" : "=l"(d) : "l"(a), "l"(d));
}
__device__ __forceinline__ float2 up2(u64 v) {
    float2 f;
    asm("mov.b64 {%0, %1}, %2;" : "=f"(f.x), "=f"(f.y) : "l"(v));
    return f;
}
__device__ __forceinline__ void red4(float* p, float a, float b, float c, float d) {
    asm volatile("red.global.add.v4.f32 [%0], {%1, %2, %3, %4};"
                 :: "l"(p), "f"(a), "f"(b), "f"(c), "f"(d) : "memory");
}
__device__ __forceinline__ void cpa16(unsigned s, const void* g) {
    asm volatile("cp.async.cg.shared.global [%0], [%1], 16;" :: "r"(s), "l"(g) : "memory");
}

// ---------------- scratch ----------------
__device__ __half g_y[(size_t)N_ATOMS * 1088];   // fp16 y (conv1 stride 544, conv2 1088)
__device__ float g_h1[N_ATOMS * H1D];
__device__ float g_h2[N_ATOMS * H2D];
__device__ float g_aa[B_G * M_M * H2D];
__device__ float g_gg[B_G * M_M * G_DIM];
__device__ int   g_aoff[M_M + 1];
__device__ int   g_asrc[EA];
__device__ float g_anorm[EA];
__device__ int   g_elist[N_EDGES];
__device__ int   g_bcnt[NBUCK];
__device__ int   g_bcur[NBUCK];

// ---------------- amino graph prep ----------------
__global__ void k_amino_prep(const int* __restrict__ aei) {
    if (threadIdx.x != 0 || blockIdx.x != 0) return;
    int deg[M_M]; float dinv[M_M]; int off[M_M + 1]; int cnt[M_M];
    for (int m = 0; m < M_M; ++m) { deg[m] = 0; cnt[m] = 0; }
    for (int e = 0; e < EA; ++e) deg[aei[EA + e]]++;
    for (int m = 0; m < M_M; ++m)
        dinv[m] = (deg[m] > 0) ? (1.0f / sqrtf((float)deg[m])) : 0.0f;
    off[0] = 0;
    for (int m = 0; m < M_M; ++m) off[m + 1] = off[m] + deg[m];
    for (int e = 0; e < EA; ++e) {
        int s = aei[e], d = aei[EA + e];
        int slot = off[d] + cnt[d]++;
        g_asrc[slot] = s;
        g_anorm[slot] = dinv[s] * dinv[d];
    }
    for (int m = 0; m <= M_M; ++m) g_aoff[m] = off[m];
}

// ---------------- parallel counting sort of edges by src bucket (src>>5) ----------------
__global__ void __launch_bounds__(256) k_szero() {
    int i = blockIdx.x * 256 + threadIdx.x;
    if (i < NBUCK) g_bcnt[i] = 0;
}
__global__ void __launch_bounds__(256) k_scount(const int* __restrict__ aei) {
    int e = blockIdx.x * 256 + threadIdx.x;
    if (e < N_EDGES) atomicAdd(&g_bcnt[aei[e] >> 5], 1);
}
__global__ void __launch_bounds__(1024) k_sprefix() {
    __shared__ int ssum[1024];
    int tid = threadIdx.x;
    int b0 = tid * 2;
    int c0 = (b0 < NBUCK) ? g_bcnt[b0] : 0;
    int c1 = (b0 + 1 < NBUCK) ? g_bcnt[b0 + 1] : 0;
    ssum[tid] = c0 + c1;
    __syncthreads();
    for (int off = 1; off < 1024; off <<= 1) {
        int v = ssum[tid];
        int add = (tid >= off) ? ssum[tid - off] : 0;
        __syncthreads();
        ssum[tid] = v + add;
        __syncthreads();
    }
    int excl = (tid > 0) ? ssum[tid - 1] : 0;
    if (b0 < NBUCK) g_bcur[b0] = excl;
    if (b0 + 1 < NBUCK) g_bcur[b0 + 1] = excl + c0;
}
__global__ void __launch_bounds__(256) k_sscatter(const int* __restrict__ aei) {
    int e = blockIdx.x * 256 + threadIdx.x;
    if (e < N_EDGES) {
        int slot = atomicAdd(&g_bcur[aei[e] >> 5], 1);
        g_elist[slot] = e;
    }
}

// ---------------- node GEMM: y[n, 17*ow] (fp16) + root+bias -> h (fp32) ----------------
__device__ __forceinline__ void stage_wtile(float* dst, int ct,
                                            const float* __restrict__ We,
                                            const float* __restrict__ be,
                                            const float* __restrict__ root,
                                            int ow_shift, int ow, int tid) {
    unsigned sb_ = (unsigned)__cvta_generic_to_shared(dst);
    for (int i = tid; i < 512; i += 256) {
        int f = i >> 4, cc = (i & 15) << 2;
        int c = ct * 64 + cc;
        int d = c >> ow_shift, o = c & (ow - 1);
        const float* src;
        if (d < 16)       src = We + (d * 32 + f) * ow + o;
        else if (d == 16) src = be + f * ow + o;
        else              src = root + f * ow + o;
        cpa16(sb_ + i * 16, src);
    }
    asm volatile("cp.async.commit_group;" ::: "memory");
}

__global__ void __launch_bounds__(256, 2) k_ygemm(const float* __restrict__ xin,
                                                  int hin_sel, int relu,
                                                  const float* __restrict__ We,
                                                  const float* __restrict__ be,
                                                  const float* __restrict__ root,
                                                  const float* __restrict__ bias,
                                                  int ow_shift, int which_h) {
    extern __shared__ float sm_[];
    float* sh = sm_;                  // 8192 floats
    float* sw0 = sm_ + 8192;          // 2048 floats
    float* sw1 = sm_ + 10240;         // 2048 floats
    float* sb = sm_ + 12288;          // 64 floats

    const int ow = 1 << ow_shift;
    const int ystride = 17 << ow_shift;
    int tid = threadIdx.x;
    int n0 = blockIdx.x * 256;
    const float* hin = hin_sel ? g_h1 : xin;
    int lane = tid & 31, wrp = tid >> 5;

    stage_wtile(sw0, blockIdx.y * 3, We, be, root, ow_shift, ow, tid);

#pragma unroll
    for (int it = 0; it < 8; ++it) {
        int n = it * 32 + lane;
        int gn = n0 + n;
        float4 v = make_float4(0.f, 0.f, 0.f, 0.f);
        if (gn < N_ATOMS) v = *(const float4*)(hin + (size_t)gn * 32 + wrp * 4);
        if (relu) {
            v.x = fmaxf(v.x, 0.f); v.y = fmaxf(v.y, 0.f);
            v.z = fmaxf(v.z, 0.f); v.w = fmaxf(v.w, 0.f);
        }
        sh[(wrp * 4 + 0) * 256 + n] = v.x;
        sh[(wrp * 4 + 1) * 256 + n] = v.y;
        sh[(wrp * 4 + 2) * 256 + n] = v.z;
        sh[(wrp * 4 + 3) * 256 + n] = v.w;
    }
    if (tid < ow) sb[tid] = bias[tid];

    int tx = tid & 7;
    int ty = tid >> 3;

    for (int ct3 = 0; ct3 < 3; ++ct3) {
        int ct = blockIdx.y * 3 + ct3;
        float* cur = (ct3 & 1) ? sw1 : sw0;
        float* nxt = (ct3 & 1) ? sw0 : sw1;
        if (ct3 < 2) {
            stage_wtile(nxt, ct + 1, We, be, root, ow_shift, ow, tid);
            asm volatile("cp.async.wait_group 1;" ::: "memory");
        } else {
            asm volatile("cp.async.wait_group 0;" ::: "memory");
        }
        __syncthreads();

        u64 acc[4][8];
#pragma unroll
        for (int p = 0; p < 4; ++p)
#pragma unroll
            for (int c = 0; c < 8; ++c) acc[p][c] = 0ull;

#pragma unroll 8
        for (int f = 0; f < 32; ++f) {
            const float* fb = sh + f * 256 + ty * 8;
            ulonglong2 hA = *(const ulonglong2*)(fb);
            ulonglong2 hB = *(const ulonglong2*)(fb + 4);
            const float* wb = cur + f * 64 + tx * 8;
            float4 wA = *(const float4*)(wb);
            float4 wB = *(const float4*)(wb + 4);
            u64 hh[4] = {hA.x, hA.y, hB.x, hB.y};
            u64 ww[8];
            ww[0] = pk2(wA.x, wA.x); ww[1] = pk2(wA.y, wA.y);
            ww[2] = pk2(wA.z, wA.z); ww[3] = pk2(wA.w, wA.w);
            ww[4] = pk2(wB.x, wB.x); ww[5] = pk2(wB.y, wB.y);
            ww[6] = pk2(wB.z, wB.z); ww[7] = pk2(wB.w, wB.w);
#pragma unroll
            for (int p = 0; p < 4; ++p)
#pragma unroll
                for (int c = 0; c < 8; ++c)
                    fma2(acc[p][c], hh[p], ww[c]);
        }

        int c0 = ct * 64 + tx * 8;
        int d = c0 >> ow_shift;
        int nb = n0 + ty * 8;
        if (d < 17) {
#pragma unroll
            for (int r = 0; r < 8; ++r) {
                int n = nb + r;
                if (n < N_ATOMS) {
                    int p = r >> 1;
                    float v[8];
#pragma unroll
                    for (int c = 0; c < 8; ++c) {
                        float2 t = up2(acc[p][c]);
                        v[c] = (r & 1) ? t.y : t.x;
                    }
                    __half2 hv2[4];
                    hv2[0] = __floats2half2_rn(v[0], v[1]);
                    hv2[1] = __floats2half2_rn(v[2], v[3]);
                    hv2[2] = __floats2half2_rn(v[4], v[5]);
                    hv2[3] = __floats2half2_rn(v[6], v[7]);
                    __half* yp = g_y + (size_t)n * ystride + c0;
                    *(uint4*)yp = *(uint4*)hv2;
                }
            }
        } else {
            int o0 = c0 - ystride;
            float* hbase = (which_h == 1 ? g_h1 : g_h2);
#pragma unroll
            for (int r = 0; r < 8; ++r) {
                int n = nb + r;
                if (n < N_ATOMS) {
                    int p = r >> 1;
                    float v[8];
#pragma unroll
                    for (int c = 0; c < 8; ++c) {
                        float2 t = up2(acc[p][c]);
                        v[c] = ((r & 1) ? t.y : t.x) + sb[o0 + c];
                    }
                    float* hp = hbase + (size_t)n * ow + o0;
                    *(float4*)(hp)     = make_float4(v[0], v[1], v[2], v[3]);
                    *(float4*)(hp + 4) = make_float4(v[4], v[5], v[6], v[7]);
                }
            }
        }
        __syncthreads();
    }
}

// ---------------- edge contraction v4: sorted list, ow/8 threads/edge, 16B fp16 loads ----------------
__global__ void __launch_bounds__(256) k_econ(const int* __restrict__ eidx,
                                              const float* __restrict__ ea_g,
                                              int ow_shift, int which_h) {
    const int ow = 1 << ow_shift;
    const int te_shift = ow_shift - 3;          // threads per edge = ow/8
    int gt = blockIdx.x * 256 + threadIdx.x;
    int ei = gt >> te_shift;
    if (ei >= N_EDGES) return;
    int e = g_elist[ei];
    int src = __ldg(eidx + e);
    int dst = __ldg(eidx + N_EDGES + e);
    int o0 = (gt & ((1 << te_shift) - 1)) << 3;  // 8 cols per thread
    const int ystride = 17 << ow_shift;
    const __half* yrow = g_y + (size_t)src * ystride + o0;
    const float4* eap = (const float4*)(ea_g + e * 16);
    float4 e0 = __ldg(eap), e1 = __ldg(eap + 1), e2 = __ldg(eap + 2), e3 = __ldg(eap + 3);
    float ew[16] = {e0.x, e0.y, e0.z, e0.w, e1.x, e1.y, e1.z, e1.w,
                    e2.x, e2.y, e2.z, e2.w, e3.x, e3.y, e3.z, e3.w};
    float acc[8];
#pragma unroll
    for (int c = 0; c < 8; ++c) acc[c] = 0.0f;
#pragma unroll
    for (int d = 0; d < 16; ++d) {
        float w = ew[d];
        uint4 raw = *(const uint4*)(yrow + (d << ow_shift));
        float2 y01 = __half22float2(*(const __half2*)&raw.x);
        float2 y23 = __half22float2(*(const __half2*)&raw.y);
        float2 y45 = __half22float2(*(const __half2*)&raw.z);
        float2 y67 = __half22float2(*(const __half2*)&raw.w);
        acc[0] = fmaf(w, y01.x, acc[0]); acc[1] = fmaf(w, y01.y, acc[1]);
        acc[2] = fmaf(w, y23.x, acc[2]); acc[3] = fmaf(w, y23.y, acc[3]);
        acc[4] = fmaf(w, y45.x, acc[4]); acc[5] = fmaf(w, y45.y, acc[5]);
        acc[6] = fmaf(w, y67.x, acc[6]); acc[7] = fmaf(w, y67.y, acc[7]);
    }
    {   // d = 16: bias slice, weight 1.0
        uint4 raw = *(const uint4*)(yrow + (16 << ow_shift));
        float2 y01 = __half22float2(*(const __half2*)&raw.x);
        float2 y23 = __half22float2(*(const __half2*)&raw.y);
        float2 y45 = __half22float2(*(const __half2*)&raw.z);
        float2 y67 = __half22float2(*(const __half2*)&raw.w);
        acc[0] += y01.x; acc[1] += y01.y; acc[2] += y23.x; acc[3] += y23.y;
        acc[4] += y45.x; acc[5] += y45.y; acc[6] += y67.x; acc[7] += y67.y;
    }
    float* hp = (which_h == 1 ? g_h1 : g_h2) + (size_t)dst * ow + o0;
    red4(hp, acc[0], acc[1], acc[2], acc[3]);
    red4(hp + 4, acc[4], acc[5], acc[6], acc[7]);
}

// ---------------- atom attention readout ----------------
__global__ void __launch_bounds__(256) k_attn(const int* __restrict__ labels,
                                              const float* __restrict__ wa_g,
                                              const float* __restrict__ ba_g) {
    extern __shared__ float sm[];
    float* sc = sm;
    float* wa = sm + 1000;
    float* red = sm + 1064;
    float* wacc = sm + 1320;

    int b = blockIdx.x, tid = threadIdx.x;
    const float* h2b = g_h2 + (size_t)b * NPG * H2D;
    if (tid < 64) wa[tid] = wa_g[tid];
    for (int i = tid; i < 8 * M_M * H2D; i += 256) wacc[i] = 0.0f;
    for (int i = tid; i < M_M * G_DIM; i += 256) g_gg[b * M_M * G_DIM + i] = 0.0f;
    __syncthreads();

    float ba = ba_g[0];
    for (int i = tid; i < NPG; i += 256) {
        const float4* r4 = (const float4*)(h2b + i * H2D);
        float s = ba;
#pragma unroll
        for (int o4 = 0; o4 < 16; ++o4) {
            float4 v = r4[o4];
            s = fmaf(fmaxf(v.x, 0.0f), wa[o4 * 4 + 0], s);
            s = fmaf(fmaxf(v.y, 0.0f), wa[o4 * 4 + 1], s);
            s = fmaf(fmaxf(v.z, 0.0f), wa[o4 * 4 + 2], s);
            s = fmaf(fmaxf(v.w, 0.0f), wa[o4 * 4 + 3], s);
        }
        sc[i] = s;
    }
    __syncthreads();
    float mx = -1e30f;
    for (int i = tid; i < NPG; i += 256) mx = fmaxf(mx, sc[i]);
    red[tid] = mx;
    __syncthreads();
    for (int s = 128; s > 0; s >>= 1) {
        if (tid < s) red[tid] = fmaxf(red[tid], red[tid + s]);
        __syncthreads();
    }
    mx = red[0];
    __syncthreads();
    float se = 0.0f;
    for (int i = tid; i < NPG; i += 256) {
        float e2 = expf(sc[i] - mx);
        sc[i] = e2;
        se += e2;
    }
    red[tid] = se;
    __syncthreads();
    for (int s = 128; s > 0; s >>= 1) {
        if (tid < s) red[tid] += red[tid + s];
        __syncthreads();
    }
    float inv = 1.0f / red[0];
    __syncthreads();

    int w = tid >> 5, lane = tid & 31;
    float* wp = wacc + w * (M_M * H2D);
    for (int i = w; i < NPG; i += 8) {
        int m = labels[b * NPG + i];
        float c = sc[i] * inv;
        const float* row = h2b + i * H2D;
        wp[m * H2D + lane]      += c * fmaxf(row[lane], 0.0f);
        wp[m * H2D + 32 + lane] += c * fmaxf(row[32 + lane], 0.0f);
    }
    __syncthreads();
    for (int i = tid; i < M_M * H2D; i += 256) {
        float s = 0.0f;
#pragma unroll
        for (int wc = 0; wc < 8; ++wc) s += wacc[wc * 3200 + i];
        g_aa[b * M_M * H2D + i] = s;
    }
}

// ---------------- ARMA (cp.async double-buffered weight chunks) ----------------
__device__ __forceinline__ void arma_mm2(u64 acc2[5][2], const float* __restrict__ xs,
                                         int xstride, int F,
                                         const float* __restrict__ ws, int m0, int o0) {
    const float* x0p = xs + m0 * xstride;
    const float* x1p = x0p + xstride;
    const float* x2p = x1p + xstride;
    const float* x3p = x2p + xstride;
    const float* x4p = x3p + xstride;
    const float* wp = ws + o0;
#pragma unroll 2
    for (int f = 0; f < F; f += 4) {
        float4 a0 = *(const float4*)(x0p + f);
        float4 a1 = *(const float4*)(x1p + f);
        float4 a2 = *(const float4*)(x2p + f);
        float4 a3 = *(const float4*)(x3p + f);
        float4 a4 = *(const float4*)(x4p + f);
        float xa[5][4] = {
            {a0.x, a0.y, a0.z, a0.w},
            {a1.x, a1.y, a1.z, a1.w},
            {a2.x, a2.y, a2.z, a2.w},
            {a3.x, a3.y, a3.z, a3.w},
            {a4.x, a4.y, a4.z, a4.w}};
#pragma unroll
        for (int j = 0; j < 4; ++j) {
            ulonglong2 wv = *(const ulonglong2*)(wp + (f + j) * G_DIM);
#pragma unroll
            for (int r = 0; r < 5; ++r) {
                u64 xv = pk2(xa[r][j], xa[r][j]);
                fma2(acc2[r][0], xv, wv.x);
                fma2(acc2[r][1], xv, wv.y);
            }
        }
    }
}

__device__ __forceinline__ void stage_chunk(float* dst, const float* __restrict__ wsrc,
                                            int c, int wrows, int tid) {
    unsigned sb = (unsigned)__cvta_generic_to_shared(dst);
    const float4* g4 = (const float4*)wsrc + (size_t)c * 1024;
    for (int i = tid; i < 1024; i += 320) {
        int row = c * 32 + (i >> 5);
        if (row < wrows) cpa16(sb + i * 16, g4 + i);
    }
    asm volatile("cp.async.commit_group;" ::: "memory");
}

__device__ void arma_gemm_pipe(u64 acc2[5][2], const float* xs, int xstride, int nch,
                               const float* __restrict__ wsrc, int wrows,
                               float* ws0, float* ws1, int tid, int m0, int o0) {
    stage_chunk(ws0, wsrc, 0, wrows, tid);
    for (int c = 0; c < nch; ++c) {
        float* cur = (c & 1) ? ws1 : ws0;
        float* nxt = (c & 1) ? ws0 : ws1;
        if (c + 1 < nch) {
            stage_chunk(nxt, wsrc, c + 1, wrows, tid);
            asm volatile("cp.async.wait_group 1;" ::: "memory");
        } else {
            asm volatile("cp.async.wait_group 0;" ::: "memory");
        }
        __syncthreads();
        arma_mm2(acc2, xs + c * 32, xstride, 32, cur, m0, o0);
        __syncthreads();
    }
}

// smem floats: x0s[8000] | bufA[6400] | ws0[4096] | ws1[4096]  = 90368 B
__global__ void __launch_bounds__(320, 2) k_arma(const float* __restrict__ aaf,
                                                 const float* __restrict__ w_init,
                                                 const float* __restrict__ w_mid,
                                                 const float* __restrict__ w_root,
                                                 const float* __restrict__ w_bias) {
    extern __shared__ float sm[];
    float* x0s = sm;
    float* bufA = sm + 8000;
    float* ws0 = sm + 14400;
    float* ws1 = sm + 18496;

    int b = blockIdx.x / K_S, k = blockIdx.x % K_S;
    int tid = threadIdx.x;
    for (int i = tid; i < 8192; i += 320) ws0[i] = 0.0f;
    for (int i = tid; i < M_M * X0PAD; i += 320) {
        int m = i / X0PAD, f = i % X0PAD;
        float v = 0.0f;
        if (f < H2D)        v = g_aa[(b * M_M + m) * H2D + f];
        else if (f < X0DIM) v = aaf[(b * M_M + m) * AAF + (f - H2D)];
        x0s[m * X0PAD + f] = v;
    }
    __syncthreads();

    int warp = tid >> 5, lane = tid & 31;
    int m0 = warp * 5, o0 = lane * 4;
    u64 acc2[5][2];

#pragma unroll
    for (int mi = 0; mi < 5; ++mi) { acc2[mi][0] = 0ull; acc2[mi][1] = 0ull; }
    arma_gemm_pipe(acc2, x0s, X0PAD, 5, w_init + (size_t)k * X0DIM * G_DIM, X0DIM,
                   ws0, ws1, tid, m0, o0);
#pragma unroll
    for (int mi = 0; mi < 5; ++mi) {
        ulonglong2 v; v.x = acc2[mi][0]; v.y = acc2[mi][1];
        *(ulonglong2*)(bufA + (m0 + mi) * G_DIM + o0) = v;
    }
    __syncthreads();

    float accf[5][4];
    for (int t = 0; t < T_L; ++t) {
        if (t > 0) {
#pragma unroll
            for (int mi = 0; mi < 5; ++mi) { acc2[mi][0] = 0ull; acc2[mi][1] = 0ull; }
            arma_gemm_pipe(acc2, bufA, G_DIM, 4,
                           w_mid + (size_t)((t - 1) * K_S + k) * G_DIM * G_DIM, G_DIM,
                           ws0, ws1, tid, m0, o0);
#pragma unroll
            for (int mi = 0; mi < 5; ++mi) {
                ulonglong2 v; v.x = acc2[mi][0]; v.y = acc2[mi][1];
                *(ulonglong2*)(bufA + (m0 + mi) * G_DIM + o0) = v;
            }
            __syncthreads();
        }
#pragma unroll
        for (int mi = 0; mi < 5; ++mi) { acc2[mi][0] = 0ull; acc2[mi][1] = 0ull; }
        arma_gemm_pipe(acc2, x0s, X0PAD, 5,
                       w_root + (size_t)(t * K_S + k) * X0DIM * G_DIM, X0DIM,
                       ws0, ws1, tid, m0, o0);
#pragma unroll
        for (int mi = 0; mi < 5; ++mi) {
            int m = m0 + mi;
            int e0 = g_aoff[m], e1 = g_aoff[m + 1];
            for (int e = e0; e < e1; ++e) {
                int s = g_asrc[e];
                u64 nr2 = pk2(g_anorm[e], g_anorm[e]);
                ulonglong2 cv = *(const ulonglong2*)(bufA + s * G_DIM + o0);
                fma2(acc2[mi][0], nr2, cv.x);
                fma2(acc2[mi][1], nr2, cv.y);
            }
        }
        ulonglong2 bv = *(const ulonglong2*)(w_bias + (t * K_S + k) * G_DIM + o0);
#pragma unroll
        for (int mi = 0; mi < 5; ++mi) {
            add2(acc2[mi][0], bv.x);
            add2(acc2[mi][1], bv.y);
            float2 lo = up2(acc2[mi][0]), hi = up2(acc2[mi][1]);
            accf[mi][0] = fmaxf(lo.x, 0.0f); accf[mi][1] = fmaxf(lo.y, 0.0f);
            accf[mi][2] = fmaxf(hi.x, 0.0f); accf[mi][3] = fmaxf(hi.y, 0.0f);
        }
        __syncthreads();
#pragma unroll
        for (int mi = 0; mi < 5; ++mi)
            *(float4*)(bufA + (m0 + mi) * G_DIM + o0) =
                make_float4(accf[mi][0], accf[mi][1], accf[mi][2], accf[mi][3]);
        __syncthreads();
    }
    const float invK = 1.0f / (float)K_S;
#pragma unroll
    for (int mi = 0; mi < 5; ++mi)
        red4(&g_gg[b * M_M * G_DIM + (m0 + mi) * G_DIM + o0],
             accf[mi][0] * invK, accf[mi][1] * invK,
             accf[mi][2] * invK, accf[mi][3] * invK);
}

// ---------------- amino attention + MLP head ----------------
__global__ void __launch_bounds__(128) k_final(const float* __restrict__ waa,
                                               const float* __restrict__ baa,
                                               const float* __restrict__ W1,
                                               const float* __restrict__ b1,
                                               const float* __restrict__ W2,
                                               const float* __restrict__ b2,
                                               const float* __restrict__ W3,
                                               const float* __restrict__ b3,
                                               const float* __restrict__ W4,
                                               const float* __restrict__ b4,
                                               float* __restrict__ out) {
    __shared__ float gs[M_M * G_DIM];
    __shared__ float sc[M_M];
    __shared__ float p[G_DIM];
    __shared__ float f1[F1D];
    __shared__ float f2[F2D];
    __shared__ float f3[F3D];
    int b = blockIdx.x, tid = threadIdx.x;
    for (int i = tid; i < M_M * G_DIM; i += 128) gs[i] = g_gg[b * M_M * G_DIM + i];
    __syncthreads();
    if (tid < M_M) {
        float s = baa[0];
#pragma unroll 4
        for (int o = 0; o < G_DIM; ++o) s = fmaf(gs[tid * G_DIM + o], waa[o], s);
        sc[tid] = s;
    }
    __syncthreads();
    if (tid == 0) {
        float mx = -1e30f;
        for (int m = 0; m < M_M; ++m) mx = fmaxf(mx, sc[m]);
        float se = 0.0f;
        for (int m = 0; m < M_M; ++m) {
            float e = expf(sc[m] - mx);
            sc[m] = e;
            se += e;
        }
        float inv = 1.0f / se;
        for (int m = 0; m < M_M; ++m) sc[m] *= inv;
    }
    __syncthreads();
    {
        float pv = 0.0f;
        for (int m = 0; m < M_M; ++m) pv = fmaf(sc[m], gs[m * G_DIM + tid], pv);
        p[tid] = pv;
    }
    __syncthreads();
    if (tid < F1D) {
        float v = b1[tid];
        for (int i = 0; i < G_DIM; ++i) v = fmaf(p[i], W1[i * F1D + tid], v);
        f1[tid] = fmaxf(v, 0.0f);
    }
    __syncthreads();
    if (tid < F2D) {
        float v = b2[tid];
        for (int i = 0; i < F1D; ++i) v = fmaf(f1[i], W2[i * F2D + tid], v);
        f2[tid] = fmaxf(v, 0.0f);
    }
    __syncthreads();
    if (tid < F3D) {
        float v = b3[tid];
        for (int i = 0; i < F2D; ++i) v = fmaf(f2[i], W3[i * F3D + tid], v);
        f3[tid] = fmaxf(v, 0.0f);
    }
    __syncthreads();
    if (tid == 0) {
        float v = b4[0];
        for (int i = 0; i < F3D; ++i) v = fmaf(f3[i], W4[i], v);
        out[b] = v;
    }
}

// ---------------- launch ----------------
extern "C" void kernel_launch(void* const* d_in, const int* in_sizes, int n_in,
                              void* d_out, int out_size) {
    const float* x              = (const float*)d_in[0];
    const float* edge_attr      = (const float*)d_in[1];
    const float* aa_features    = (const float*)d_in[2];
    const int*   edge_index     = (const int*)d_in[3];
    const int*   monomer_labels = (const int*)d_in[4];
    const int*   amino_edge_idx = (const int*)d_in[5];
    const float* W_e1   = (const float*)d_in[6];
    const float* b_e1   = (const float*)d_in[7];
    const float* root1  = (const float*)d_in[8];
    const float* bias1  = (const float*)d_in[9];
    const float* W_e2   = (const float*)d_in[10];
    const float* b_e2   = (const float*)d_in[11];
    const float* root2  = (const float*)d_in[12];
    const float* bias2  = (const float*)d_in[13];
    const float* Wa_atom = (const float*)d_in[14];
    const float* ba_atom = (const float*)d_in[15];
    const float* arma_init_w = (const float*)d_in[16];
    const float* arma_w      = (const float*)d_in[17];
    const float* arma_root_w = (const float*)d_in[18];
    const float* arma_bias   = (const float*)d_in[19];
    const float* Wa_aa = (const float*)d_in[20];
    const float* ba_aa = (const float*)d_in[21];
    const float* W1 = (const float*)d_in[22];
    const float* b1 = (const float*)d_in[23];
    const float* W2 = (const float*)d_in[24];
    const float* b2 = (const float*)d_in[25];
    const float* W3 = (const float*)d_in[26];
    const float* b3 = (const float*)d_in[27];
    const float* W4 = (const float*)d_in[28];
    const float* b4 = (const float*)d_in[29];
    float* out = (float*)d_out;

    const int YG_SMEM   = (8192 + 2048 + 2048 + 64) * 4;      // 49408 B
    const int ATTN_SMEM = (1000 + 64 + 256 + 25600) * 4;      // 107680 B
    const int ARMA_SMEM = (8000 + 6400 + 8192) * 4;           // 90368 B
    cudaFuncSetAttribute(k_ygemm, cudaFuncAttributeMaxDynamicSharedMemorySize, YG_SMEM);
    cudaFuncSetAttribute(k_attn, cudaFuncAttributeMaxDynamicSharedMemorySize, ATTN_SMEM);
    cudaFuncSetAttribute(k_arma, cudaFuncAttributeMaxDynamicSharedMemorySize, ARMA_SMEM);

    dim3 YG1((N_ATOMS + 255) / 256, 3);      // conv1: 9 col tiles
    dim3 YG2((N_ATOMS + 255) / 256, 6);      // conv2: 18 col tiles
    const int EC1_GRID = (N_EDGES * 4 + 255) / 256;    // 1563 (4 thr/edge)
    const int EC2_GRID = (N_EDGES * 8 + 255) / 256;    // 3125 (8 thr/edge)
    const int EGRID = (N_EDGES + 255) / 256;

    k_amino_prep<<<1, 32>>>(amino_edge_idx);
    k_szero<<<(NBUCK + 255) / 256, 256>>>();
    k_scount<<<EGRID, 256>>>(edge_index);
    k_sprefix<<<1, 1024>>>();
    k_sscatter<<<EGRID, 256>>>(edge_index);

    // conv1
    k_ygemm<<<YG1, 256, YG_SMEM>>>(x, 0, 0, W_e1, b_e1, root1, bias1, 5, 1);
    k_econ<<<EC1_GRID, 256>>>(edge_index, edge_attr, 5, 1);

    // conv2 (merged, full 64-wide)
    k_ygemm<<<YG2, 256, YG_SMEM>>>(x, 1, 1, W_e2, b_e2, root2, bias2, 6, 2);
    k_econ<<<EC2_GRID, 256>>>(edge_index, edge_attr, 6, 2);

    k_attn<<<B_G, 256, ATTN_SMEM>>>(monomer_labels, Wa_atom, ba_atom);
    k_arma<<<B_G * K_S, 320, ARMA_SMEM>>>(aa_features, arma_init_w, arma_w, arma_root_w, arma_bias);
    k_final<<<B_G, 128>>>(Wa_aa, ba_aa, W1, b1, W2, b2, W3, b3, W4, b4, out);
}

// round 16
// speedup vs baseline: 1.0501x; 1.0501x over previous
#include <cuda_runtime.h>
#include <cuda_fp16.h>
#include <math.h>

#define N_ATOMS 50000
#define N_EDGES 100000
#define B_G 50
#define M_M 50
#define NPG 1000
#define DIN 32
#define H1D 32
#define H2D 64
#define DE 16
#define AAF 95
#define G_DIM 128
#define K_S 3
#define T_L 6
#define EA 98
#define F1D 64
#define F2D 32
#define F3D 16
#define X0DIM 159
#define X0PAD 160

typedef unsigned long long u64;

// ---------------- f32x2 helpers ----------------
__device__ __forceinline__ u64 pk2(float a, float b) {
    u64 r;
    asm("mov.b64 %0, {%1, %2};" : "=l"(r) : "f"(a), "f"(b));
    return r;
}
__device__ __forceinline__ void fma2(u64& d, u64 a, u64 b) {
    asm("fma.rn.f32x2 %0, %1, %2, %3;" : "=l"(d) : "l"(a), "l"(b), "l"(d));
}
__device__ __forceinline__ void add2(u64& d, u64 a) {
    asm("add.rn.f32x2 %0, %1, %2;" : "=l"(d) : "l"(a), "l"(d));
}
__device__ __forceinline__ float2 up2(u64 v) {
    float2 f;
    asm("mov.b64 {%0, %1}, %2;" : "=f"(f.x), "=f"(f.y) : "l"(v));
    return f;
}
__device__ __forceinline__ void red4(float* p, float a, float b, float c, float d) {
    asm volatile("red.global.add.v4.f32 [%0], {%1, %2, %3, %4};"
                 :: "l"(p), "f"(a), "f"(b), "f"(c), "f"(d) : "memory");
}
__device__ __forceinline__ void cpa16(unsigned s, const void* g) {
    asm volatile("cp.async.cg.shared.global [%0], [%1], 16;" :: "r"(s), "l"(g) : "memory");
}

// ---------------- scratch ----------------
__device__ __half g_y[(size_t)N_ATOMS * 1088];   // fp16 y (conv1 stride 544, conv2 1088)
__device__ float g_h1[N_ATOMS * H1D];
__device__ float g_h2[N_ATOMS * H2D];
__device__ float g_aa[B_G * M_M * H2D];
__device__ float g_gg[B_G * M_M * G_DIM];
__device__ int   g_aoff[M_M + 1];
__device__ int   g_asrc[EA];
__device__ float g_anorm[EA];

// ---------------- amino graph prep ----------------
__global__ void k_amino_prep(const int* __restrict__ aei) {
    if (threadIdx.x != 0 || blockIdx.x != 0) return;
    int deg[M_M]; float dinv[M_M]; int off[M_M + 1]; int cnt[M_M];
    for (int m = 0; m < M_M; ++m) { deg[m] = 0; cnt[m] = 0; }
    for (int e = 0; e < EA; ++e) deg[aei[EA + e]]++;
    for (int m = 0; m < M_M; ++m)
        dinv[m] = (deg[m] > 0) ? (1.0f / sqrtf((float)deg[m])) : 0.0f;
    off[0] = 0;
    for (int m = 0; m < M_M; ++m) off[m + 1] = off[m] + deg[m];
    for (int e = 0; e < EA; ++e) {
        int s = aei[e], d = aei[EA + e];
        int slot = off[d] + cnt[d]++;
        g_asrc[slot] = s;
        g_anorm[slot] = dinv[s] * dinv[d];
    }
    for (int m = 0; m <= M_M; ++m) g_aoff[m] = off[m];
}

// ---------------- node GEMM: y[n, 17*ow] (fp16) + root+bias -> h (fp32) ----------------
__device__ __forceinline__ void stage_wtile(float* dst, int ct,
                                            const float* __restrict__ We,
                                            const float* __restrict__ be,
                                            const float* __restrict__ root,
                                            int ow_shift, int ow, int tid) {
    unsigned sb_ = (unsigned)__cvta_generic_to_shared(dst);
    for (int i = tid; i < 512; i += 256) {
        int f = i >> 4, cc = (i & 15) << 2;
        int c = ct * 64 + cc;
        int d = c >> ow_shift, o = c & (ow - 1);
        const float* src;
        if (d < 16)       src = We + (d * 32 + f) * ow + o;
        else if (d == 16) src = be + f * ow + o;
        else              src = root + f * ow + o;
        cpa16(sb_ + i * 16, src);
    }
    asm volatile("cp.async.commit_group;" ::: "memory");
}

__global__ void __launch_bounds__(256, 2) k_ygemm(const float* __restrict__ xin,
                                                  int hin_sel, int relu,
                                                  const float* __restrict__ We,
                                                  const float* __restrict__ be,
                                                  const float* __restrict__ root,
                                                  const float* __restrict__ bias,
                                                  int ow_shift, int which_h) {
    extern __shared__ float sm_[];
    float* sh = sm_;                  // 8192 floats
    float* sw0 = sm_ + 8192;          // 2048 floats
    float* sw1 = sm_ + 10240;         // 2048 floats
    float* sb = sm_ + 12288;          // 64 floats

    const int ow = 1 << ow_shift;
    const int ystride = 17 << ow_shift;
    int tid = threadIdx.x;
    int n0 = blockIdx.x * 256;
    const float* hin = hin_sel ? g_h1 : xin;
    int lane = tid & 31, wrp = tid >> 5;

    stage_wtile(sw0, blockIdx.y * 3, We, be, root, ow_shift, ow, tid);

#pragma unroll
    for (int it = 0; it < 8; ++it) {
        int n = it * 32 + lane;
        int gn = n0 + n;
        float4 v = make_float4(0.f, 0.f, 0.f, 0.f);
        if (gn < N_ATOMS) v = *(const float4*)(hin + (size_t)gn * 32 + wrp * 4);
        if (relu) {
            v.x = fmaxf(v.x, 0.f); v.y = fmaxf(v.y, 0.f);
            v.z = fmaxf(v.z, 0.f); v.w = fmaxf(v.w, 0.f);
        }
        sh[(wrp * 4 + 0) * 256 + n] = v.x;
        sh[(wrp * 4 + 1) * 256 + n] = v.y;
        sh[(wrp * 4 + 2) * 256 + n] = v.z;
        sh[(wrp * 4 + 3) * 256 + n] = v.w;
    }
    if (tid < ow) sb[tid] = bias[tid];

    int tx = tid & 7;
    int ty = tid >> 3;

    for (int ct3 = 0; ct3 < 3; ++ct3) {
        int ct = blockIdx.y * 3 + ct3;
        float* cur = (ct3 & 1) ? sw1 : sw0;
        float* nxt = (ct3 & 1) ? sw0 : sw1;
        if (ct3 < 2) {
            stage_wtile(nxt, ct + 1, We, be, root, ow_shift, ow, tid);
            asm volatile("cp.async.wait_group 1;" ::: "memory");
        } else {
            asm volatile("cp.async.wait_group 0;" ::: "memory");
        }
        __syncthreads();

        u64 acc[4][8];
#pragma unroll
        for (int p = 0; p < 4; ++p)
#pragma unroll
            for (int c = 0; c < 8; ++c) acc[p][c] = 0ull;

#pragma unroll 8
        for (int f = 0; f < 32; ++f) {
            const float* fb = sh + f * 256 + ty * 8;
            ulonglong2 hA = *(const ulonglong2*)(fb);
            ulonglong2 hB = *(const ulonglong2*)(fb + 4);
            const float* wb = cur + f * 64 + tx * 8;
            float4 wA = *(const float4*)(wb);
            float4 wB = *(const float4*)(wb + 4);
            u64 hh[4] = {hA.x, hA.y, hB.x, hB.y};
            u64 ww[8];
            ww[0] = pk2(wA.x, wA.x); ww[1] = pk2(wA.y, wA.y);
            ww[2] = pk2(wA.z, wA.z); ww[3] = pk2(wA.w, wA.w);
            ww[4] = pk2(wB.x, wB.x); ww[5] = pk2(wB.y, wB.y);
            ww[6] = pk2(wB.z, wB.z); ww[7] = pk2(wB.w, wB.w);
#pragma unroll
            for (int p = 0; p < 4; ++p)
#pragma unroll
                for (int c = 0; c < 8; ++c)
                    fma2(acc[p][c], hh[p], ww[c]);
        }

        int c0 = ct * 64 + tx * 8;
        int d = c0 >> ow_shift;
        int nb = n0 + ty * 8;
        if (d < 17) {
#pragma unroll
            for (int r = 0; r < 8; ++r) {
                int n = nb + r;
                if (n < N_ATOMS) {
                    int p = r >> 1;
                    float v[8];
#pragma unroll
                    for (int c = 0; c < 8; ++c) {
                        float2 t = up2(acc[p][c]);
                        v[c] = (r & 1) ? t.y : t.x;
                    }
                    __half2 hv2[4];
                    hv2[0] = __floats2half2_rn(v[0], v[1]);
                    hv2[1] = __floats2half2_rn(v[2], v[3]);
                    hv2[2] = __floats2half2_rn(v[4], v[5]);
                    hv2[3] = __floats2half2_rn(v[6], v[7]);
                    __half* yp = g_y + (size_t)n * ystride + c0;
                    *(uint4*)yp = *(uint4*)hv2;
                }
            }
        } else {
            int o0 = c0 - ystride;
            float* hbase = (which_h == 1 ? g_h1 : g_h2);
#pragma unroll
            for (int r = 0; r < 8; ++r) {
                int n = nb + r;
                if (n < N_ATOMS) {
                    int p = r >> 1;
                    float v[8];
#pragma unroll
                    for (int c = 0; c < 8; ++c) {
                        float2 t = up2(acc[p][c]);
                        v[c] = ((r & 1) ? t.y : t.x) + sb[o0 + c];
                    }
                    float* hp = hbase + (size_t)n * ow + o0;
                    *(float4*)(hp)     = make_float4(v[0], v[1], v[2], v[3]);
                    *(float4*)(hp + 4) = make_float4(v[4], v[5], v[6], v[7]);
                }
            }
        }
        __syncthreads();
    }
}

// ---------------- edge contraction: natural order, ow/8 threads/edge, 16B fp16 loads ----------------
__global__ void __launch_bounds__(256) k_econ(const int* __restrict__ eidx,
                                              const float* __restrict__ ea_g,
                                              int ow_shift, int which_h) {
    const int ow = 1 << ow_shift;
    const int te_shift = ow_shift - 3;          // threads per edge = ow/8
    int gt = blockIdx.x * 256 + threadIdx.x;
    int e = gt >> te_shift;
    if (e >= N_EDGES) return;
    int src = __ldg(eidx + e);
    int dst = __ldg(eidx + N_EDGES + e);
    int o0 = (gt & ((1 << te_shift) - 1)) << 3;  // 8 cols per thread
    const int ystride = 17 << ow_shift;
    const __half* yrow = g_y + (size_t)src * ystride + o0;
    const float4* eap = (const float4*)(ea_g + e * 16);
    float4 e0 = __ldg(eap), e1 = __ldg(eap + 1), e2 = __ldg(eap + 2), e3 = __ldg(eap + 3);
    float ew[16] = {e0.x, e0.y, e0.z, e0.w, e1.x, e1.y, e1.z, e1.w,
                    e2.x, e2.y, e2.z, e2.w, e3.x, e3.y, e3.z, e3.w};
    float acc[8];
#pragma unroll
    for (int c = 0; c < 8; ++c) acc[c] = 0.0f;
#pragma unroll
    for (int d = 0; d < 16; ++d) {
        float w = ew[d];
        uint4 raw = *(const uint4*)(yrow + (d << ow_shift));
        float2 y01 = __half22float2(*(const __half2*)&raw.x);
        float2 y23 = __half22float2(*(const __half2*)&raw.y);
        float2 y45 = __half22float2(*(const __half2*)&raw.z);
        float2 y67 = __half22float2(*(const __half2*)&raw.w);
        acc[0] = fmaf(w, y01.x, acc[0]); acc[1] = fmaf(w, y01.y, acc[1]);
        acc[2] = fmaf(w, y23.x, acc[2]); acc[3] = fmaf(w, y23.y, acc[3]);
        acc[4] = fmaf(w, y45.x, acc[4]); acc[5] = fmaf(w, y45.y, acc[5]);
        acc[6] = fmaf(w, y67.x, acc[6]); acc[7] = fmaf(w, y67.y, acc[7]);
    }
    {   // d = 16: bias slice, weight 1.0
        uint4 raw = *(const uint4*)(yrow + (16 << ow_shift));
        float2 y01 = __half22float2(*(const __half2*)&raw.x);
        float2 y23 = __half22float2(*(const __half2*)&raw.y);
        float2 y45 = __half22float2(*(const __half2*)&raw.z);
        float2 y67 = __half22float2(*(const __half2*)&raw.w);
        acc[0] += y01.x; acc[1] += y01.y; acc[2] += y23.x; acc[3] += y23.y;
        acc[4] += y45.x; acc[5] += y45.y; acc[6] += y67.x; acc[7] += y67.y;
    }
    float* hp = (which_h == 1 ? g_h1 : g_h2) + (size_t)dst * ow + o0;
    red4(hp, acc[0], acc[1], acc[2], acc[3]);
    red4(hp + 4, acc[4], acc[5], acc[6], acc[7]);
}

// ---------------- atom attention readout ----------------
__global__ void __launch_bounds__(256) k_attn(const int* __restrict__ labels,
                                              const float* __restrict__ wa_g,
                                              const float* __restrict__ ba_g) {
    extern __shared__ float sm[];
    float* sc = sm;
    float* wa = sm + 1000;
    float* red = sm + 1064;
    float* wacc = sm + 1320;

    int b = blockIdx.x, tid = threadIdx.x;
    const float* h2b = g_h2 + (size_t)b * NPG * H2D;
    if (tid < 64) wa[tid] = wa_g[tid];
    for (int i = tid; i < 8 * M_M * H2D; i += 256) wacc[i] = 0.0f;
    for (int i = tid; i < M_M * G_DIM; i += 256) g_gg[b * M_M * G_DIM + i] = 0.0f;
    __syncthreads();

    float ba = ba_g[0];
    for (int i = tid; i < NPG; i += 256) {
        const float4* r4 = (const float4*)(h2b + i * H2D);
        float s = ba;
#pragma unroll
        for (int o4 = 0; o4 < 16; ++o4) {
            float4 v = r4[o4];
            s = fmaf(fmaxf(v.x, 0.0f), wa[o4 * 4 + 0], s);
            s = fmaf(fmaxf(v.y, 0.0f), wa[o4 * 4 + 1], s);
            s = fmaf(fmaxf(v.z, 0.0f), wa[o4 * 4 + 2], s);
            s = fmaf(fmaxf(v.w, 0.0f), wa[o4 * 4 + 3], s);
        }
        sc[i] = s;
    }
    __syncthreads();
    float mx = -1e30f;
    for (int i = tid; i < NPG; i += 256) mx = fmaxf(mx, sc[i]);
    red[tid] = mx;
    __syncthreads();
    for (int s = 128; s > 0; s >>= 1) {
        if (tid < s) red[tid] = fmaxf(red[tid], red[tid + s]);
        __syncthreads();
    }
    mx = red[0];
    __syncthreads();
    float se = 0.0f;
    for (int i = tid; i < NPG; i += 256) {
        float e2 = expf(sc[i] - mx);
        sc[i] = e2;
        se += e2;
    }
    red[tid] = se;
    __syncthreads();
    for (int s = 128; s > 0; s >>= 1) {
        if (tid < s) red[tid] += red[tid + s];
        __syncthreads();
    }
    float inv = 1.0f / red[0];
    __syncthreads();

    int w = tid >> 5, lane = tid & 31;
    float* wp = wacc + w * (M_M * H2D);
    for (int i = w; i < NPG; i += 8) {
        int m = labels[b * NPG + i];
        float c = sc[i] * inv;
        const float* row = h2b + i * H2D;
        wp[m * H2D + lane]      += c * fmaxf(row[lane], 0.0f);
        wp[m * H2D + 32 + lane] += c * fmaxf(row[32 + lane], 0.0f);
    }
    __syncthreads();
    for (int i = tid; i < M_M * H2D; i += 256) {
        float s = 0.0f;
#pragma unroll
        for (int wc = 0; wc < 8; ++wc) s += wacc[wc * 3200 + i];
        g_aa[b * M_M * H2D + i] = s;
    }
}

// ---------------- ARMA (cp.async double-buffered weight chunks) ----------------
__device__ __forceinline__ void arma_mm2(u64 acc2[5][2], const float* __restrict__ xs,
                                         int xstride, int F,
                                         const float* __restrict__ ws, int m0, int o0) {
    const float* x0p = xs + m0 * xstride;
    const float* x1p = x0p + xstride;
    const float* x2p = x1p + xstride;
    const float* x3p = x2p + xstride;
    const float* x4p = x3p + xstride;
    const float* wp = ws + o0;
#pragma unroll 2
    for (int f = 0; f < F; f += 4) {
        float4 a0 = *(const float4*)(x0p + f);
        float4 a1 = *(const float4*)(x1p + f);
        float4 a2 = *(const float4*)(x2p + f);
        float4 a3 = *(const float4*)(x3p + f);
        float4 a4 = *(const float4*)(x4p + f);
        float xa[5][4] = {
            {a0.x, a0.y, a0.z, a0.w},
            {a1.x, a1.y, a1.z, a1.w},
            {a2.x, a2.y, a2.z, a2.w},
            {a3.x, a3.y, a3.z, a3.w},
            {a4.x, a4.y, a4.z, a4.w}};
#pragma unroll
        for (int j = 0; j < 4; ++j) {
            ulonglong2 wv = *(const ulonglong2*)(wp + (f + j) * G_DIM);
#pragma unroll
            for (int r = 0; r < 5; ++r) {
                u64 xv = pk2(xa[r][j], xa[r][j]);
                fma2(acc2[r][0], xv, wv.x);
                fma2(acc2[r][1], xv, wv.y);
            }
        }
    }
}

__device__ __forceinline__ void stage_chunk(float* dst, const float* __restrict__ wsrc,
                                            int c, int wrows, int tid) {
    unsigned sb = (unsigned)__cvta_generic_to_shared(dst);
    const float4* g4 = (const float4*)wsrc + (size_t)c * 1024;
    for (int i = tid; i < 1024; i += 320) {
        int row = c * 32 + (i >> 5);
        if (row < wrows) cpa16(sb + i * 16, g4 + i);
    }
    asm volatile("cp.async.commit_group;" ::: "memory");
}

__device__ void arma_gemm_pipe(u64 acc2[5][2], const float* xs, int xstride, int nch,
                               const float* __restrict__ wsrc, int wrows,
                               float* ws0, float* ws1, int tid, int m0, int o0) {
    stage_chunk(ws0, wsrc, 0, wrows, tid);
    for (int c = 0; c < nch; ++c) {
        float* cur = (c & 1) ? ws1 : ws0;
        float* nxt = (c & 1) ? ws0 : ws1;
        if (c + 1 < nch) {
            stage_chunk(nxt, wsrc, c + 1, wrows, tid);
            asm volatile("cp.async.wait_group 1;" ::: "memory");
        } else {
            asm volatile("cp.async.wait_group 0;" ::: "memory");
        }
        __syncthreads();
        arma_mm2(acc2, xs + c * 32, xstride, 32, cur, m0, o0);
        __syncthreads();
    }
}

// smem floats: x0s[8000] | bufA[6400] | ws0[4096] | ws1[4096]  = 90368 B
__global__ void __launch_bounds__(320, 2) k_arma(const float* __restrict__ aaf,
                                                 const float* __restrict__ w_init,
                                                 const float* __restrict__ w_mid,
                                                 const float* __restrict__ w_root,
                                                 const float* __restrict__ w_bias) {
    extern __shared__ float sm[];
    float* x0s = sm;
    float* bufA = sm + 8000;
    float* ws0 = sm + 14400;
    float* ws1 = sm + 18496;

    int b = blockIdx.x / K_S, k = blockIdx.x % K_S;
    int tid = threadIdx.x;
    for (int i = tid; i < 8192; i += 320) ws0[i] = 0.0f;
    for (int i = tid; i < M_M * X0PAD; i += 320) {
        int m = i / X0PAD, f = i % X0PAD;
        float v = 0.0f;
        if (f < H2D)        v = g_aa[(b * M_M + m) * H2D + f];
        else if (f < X0DIM) v = aaf[(b * M_M + m) * AAF + (f - H2D)];
        x0s[m * X0PAD + f] = v;
    }
    __syncthreads();

    int warp = tid >> 5, lane = tid & 31;
    int m0 = warp * 5, o0 = lane * 4;
    u64 acc2[5][2];

#pragma unroll
    for (int mi = 0; mi < 5; ++mi) { acc2[mi][0] = 0ull; acc2[mi][1] = 0ull; }
    arma_gemm_pipe(acc2, x0s, X0PAD, 5, w_init + (size_t)k * X0DIM * G_DIM, X0DIM,
                   ws0, ws1, tid, m0, o0);
#pragma unroll
    for (int mi = 0; mi < 5; ++mi) {
        ulonglong2 v; v.x = acc2[mi][0]; v.y = acc2[mi][1];
        *(ulonglong2*)(bufA + (m0 + mi) * G_DIM + o0) = v;
    }
    __syncthreads();

    float accf[5][4];
    for (int t = 0; t < T_L; ++t) {
        if (t > 0) {
#pragma unroll
            for (int mi = 0; mi < 5; ++mi) { acc2[mi][0] = 0ull; acc2[mi][1] = 0ull; }
            arma_gemm_pipe(acc2, bufA, G_DIM, 4,
                           w_mid + (size_t)((t - 1) * K_S + k) * G_DIM * G_DIM, G_DIM,
                           ws0, ws1, tid, m0, o0);
#pragma unroll
            for (int mi = 0; mi < 5; ++mi) {
                ulonglong2 v; v.x = acc2[mi][0]; v.y = acc2[mi][1];
                *(ulonglong2*)(bufA + (m0 + mi) * G_DIM + o0) = v;
            }
            __syncthreads();
        }
#pragma unroll
        for (int mi = 0; mi < 5; ++mi) { acc2[mi][0] = 0ull; acc2[mi][1] = 0ull; }
        arma_gemm_pipe(acc2, x0s, X0PAD, 5,
                       w_root + (size_t)(t * K_S + k) * X0DIM * G_DIM, X0DIM,
                       ws0, ws1, tid, m0, o0);
#pragma unroll
        for (int mi = 0; mi < 5; ++mi) {
            int m = m0 + mi;
            int e0 = g_aoff[m], e1 = g_aoff[m + 1];
            for (int e = e0; e < e1; ++e) {
                int s = g_asrc[e];
                u64 nr2 = pk2(g_anorm[e], g_anorm[e]);
                ulonglong2 cv = *(const ulonglong2*)(bufA + s * G_DIM + o0);
                fma2(acc2[mi][0], nr2, cv.x);
                fma2(acc2[mi][1], nr2, cv.y);
            }
        }
        ulonglong2 bv = *(const ulonglong2*)(w_bias + (t * K_S + k) * G_DIM + o0);
#pragma unroll
        for (int mi = 0; mi < 5; ++mi) {
            add2(acc2[mi][0], bv.x);
            add2(acc2[mi][1], bv.y);
            float2 lo = up2(acc2[mi][0]), hi = up2(acc2[mi][1]);
            accf[mi][0] = fmaxf(lo.x, 0.0f); accf[mi][1] = fmaxf(lo.y, 0.0f);
            accf[mi][2] = fmaxf(hi.x, 0.0f); accf[mi][3] = fmaxf(hi.y, 0.0f);
        }
        __syncthreads();
#pragma unroll
        for (int mi = 0; mi < 5; ++mi)
            *(float4*)(bufA + (m0 + mi) * G_DIM + o0) =
                make_float4(accf[mi][0], accf[mi][1], accf[mi][2], accf[mi][3]);
        __syncthreads();
    }
    const float invK = 1.0f / (float)K_S;
#pragma unroll
    for (int mi = 0; mi < 5; ++mi)
        red4(&g_gg[b * M_M * G_DIM + (m0 + mi) * G_DIM + o0],
             accf[mi][0] * invK, accf[mi][1] * invK,
             accf[mi][2] * invK, accf[mi][3] * invK);
}

// ---------------- amino attention + MLP head ----------------
__global__ void __launch_bounds__(128) k_final(const float* __restrict__ waa,
                                               const float* __restrict__ baa,
                                               const float* __restrict__ W1,
                                               const float* __restrict__ b1,
                                               const float* __restrict__ W2,
                                               const float* __restrict__ b2,
                                               const float* __restrict__ W3,
                                               const float* __restrict__ b3,
                                               const float* __restrict__ W4,
                                               const float* __restrict__ b4,
                                               float* __restrict__ out) {
    __shared__ float gs[M_M * G_DIM];
    __shared__ float sc[M_M];
    __shared__ float p[G_DIM];
    __shared__ float f1[F1D];
    __shared__ float f2[F2D];
    __shared__ float f3[F3D];
    int b = blockIdx.x, tid = threadIdx.x;
    for (int i = tid; i < M_M * G_DIM; i += 128) gs[i] = g_gg[b * M_M * G_DIM + i];
    __syncthreads();
    if (tid < M_M) {
        float s = baa[0];
#pragma unroll 4
        for (int o = 0; o < G_DIM; ++o) s = fmaf(gs[tid * G_DIM + o], waa[o], s);
        sc[tid] = s;
    }
    __syncthreads();
    if (tid == 0) {
        float mx = -1e30f;
        for (int m = 0; m < M_M; ++m) mx = fmaxf(mx, sc[m]);
        float se = 0.0f;
        for (int m = 0; m < M_M; ++m) {
            float e = expf(sc[m] - mx);
            sc[m] = e;
            se += e;
        }
        float inv = 1.0f / se;
        for (int m = 0; m < M_M; ++m) sc[m] *= inv;
    }
    __syncthreads();
    {
        float pv = 0.0f;
        for (int m = 0; m < M_M; ++m) pv = fmaf(sc[m], gs[m * G_DIM + tid], pv);
        p[tid] = pv;
    }
    __syncthreads();
    if (tid < F1D) {
        float v = b1[tid];
        for (int i = 0; i < G_DIM; ++i) v = fmaf(p[i], W1[i * F1D + tid], v);
        f1[tid] = fmaxf(v, 0.0f);
    }
    __syncthreads();
    if (tid < F2D) {
        float v = b2[tid];
        for (int i = 0; i < F1D; ++i) v = fmaf(f1[i], W2[i * F2D + tid], v);
        f2[tid] = fmaxf(v, 0.0f);
    }
    __syncthreads();
    if (tid < F3D) {
        float v = b3[tid];
        for (int i = 0; i < F2D; ++i) v = fmaf(f2[i], W3[i * F3D + tid], v);
        f3[tid] = fmaxf(v, 0.0f);
    }
    __syncthreads();
    if (tid == 0) {
        float v = b4[0];
        for (int i = 0; i < F3D; ++i) v = fmaf(f3[i], W4[i], v);
        out[b] = v;
    }
}

// ---------------- launch ----------------
extern "C" void kernel_launch(void* const* d_in, const int* in_sizes, int n_in,
                              void* d_out, int out_size) {
    const float* x              = (const float*)d_in[0];
    const float* edge_attr      = (const float*)d_in[1];
    const float* aa_features    = (const float*)d_in[2];
    const int*   edge_index     = (const int*)d_in[3];
    const int*   monomer_labels = (const int*)d_in[4];
    const int*   amino_edge_idx = (const int*)d_in[5];
    const float* W_e1   = (const float*)d_in[6];
    const float* b_e1   = (const float*)d_in[7];
    const float* root1  = (const float*)d_in[8];
    const float* bias1  = (const float*)d_in[9];
    const float* W_e2   = (const float*)d_in[10];
    const float* b_e2   = (const float*)d_in[11];
    const float* root2  = (const float*)d_in[12];
    const float* bias2  = (const float*)d_in[13];
    const float* Wa_atom = (const float*)d_in[14];
    const float* ba_atom = (const float*)d_in[15];
    const float* arma_init_w = (const float*)d_in[16];
    const float* arma_w      = (const float*)d_in[17];
    const float* arma_root_w = (const float*)d_in[18];
    const float* arma_bias   = (const float*)d_in[19];
    const float* Wa_aa = (const float*)d_in[20];
    const float* ba_aa = (const float*)d_in[21];
    const float* W1 = (const float*)d_in[22];
    const float* b1 = (const float*)d_in[23];
    const float* W2 = (const float*)d_in[24];
    const float* b2 = (const float*)d_in[25];
    const float* W3 = (const float*)d_in[26];
    const float* b3 = (const float*)d_in[27];
    const float* W4 = (const float*)d_in[28];
    const float* b4 = (const float*)d_in[29];
    float* out = (float*)d_out;

    const int YG_SMEM   = (8192 + 2048 + 2048 + 64) * 4;      // 49408 B
    const int ATTN_SMEM = (1000 + 64 + 256 + 25600) * 4;      // 107680 B
    const int ARMA_SMEM = (8000 + 6400 + 8192) * 4;           // 90368 B
    cudaFuncSetAttribute(k_ygemm, cudaFuncAttributeMaxDynamicSharedMemorySize, YG_SMEM);
    cudaFuncSetAttribute(k_attn, cudaFuncAttributeMaxDynamicSharedMemorySize, ATTN_SMEM);
    cudaFuncSetAttribute(k_arma, cudaFuncAttributeMaxDynamicSharedMemorySize, ARMA_SMEM);

    dim3 YG1((N_ATOMS + 255) / 256, 3);      // conv1: 9 col tiles
    dim3 YG2((N_ATOMS + 255) / 256, 6);      // conv2: 18 col tiles
    const int EC1_GRID = (N_EDGES * 4 + 255) / 256;    // 1563 (4 thr/edge)
    const int EC2_GRID = (N_EDGES * 8 + 255) / 256;    // 3125 (8 thr/edge)

    k_amino_prep<<<1, 32>>>(amino_edge_idx);

    // conv1
    k_ygemm<<<YG1, 256, YG_SMEM>>>(x, 0, 0, W_e1, b_e1, root1, bias1, 5, 1);
    k_econ<<<EC1_GRID, 256>>>(edge_index, edge_attr, 5, 1);

    // conv2 (merged, full 64-wide)
    k_ygemm<<<YG2, 256, YG_SMEM>>>(x, 1, 1, W_e2, b_e2, root2, bias2, 6, 2);
    k_econ<<<EC2_GRID, 256>>>(edge_index, edge_attr, 6, 2);

    k_attn<<<B_G, 256, ATTN_SMEM>>>(monomer_labels, Wa_atom, ba_atom);
    k_arma<<<B_G * K_S, 320, ARMA_SMEM>>>(aa_features, arma_init_w, arma_w, arma_root_w, arma_bias);
    k_final<<<B_G, 128>>>(Wa_aa, ba_aa, W1, b1, W2, b2, W3, b3, W4, b4, out);
}